// round 3
// baseline (speedup 1.0000x reference)
#include <cuda_runtime.h>
#include <cuda_bf16.h>

#define N_NODES   200000
#define N_EDGES   3200000
#define N_GRAPHS  4000

// Scratch (device globals; no runtime allocation allowed)
__device__ float g_deg[N_NODES];            // in-degree (layer 1 & 2 share)
__device__ float g_agg[N_NODES * 64];       // layer1 uses [N][32] layout, layer2 [N][64]
__device__ float g_h1 [N_NODES * 64];       // relu(conv1) output
__device__ float g_pool[N_GRAPHS * 64];     // pooled sums
__device__ float g_cnt [N_GRAPHS];          // nodes per graph

__device__ __forceinline__ void red_add_v4(float* p, float4 v) {
    asm volatile("red.global.add.v4.f32 [%0], {%1,%2,%3,%4};"
                 :: "l"(p), "f"(v.x), "f"(v.y), "f"(v.z), "f"(v.w) : "memory");
}

// ---------------------------------------------------------------------------
// Zeroing
// ---------------------------------------------------------------------------
__global__ __launch_bounds__(256) void k_zero_all() {
    long long i = (long long)blockIdx.x * blockDim.x + threadIdx.x;
    long long stride = (long long)gridDim.x * blockDim.x;
    float4 z = make_float4(0.f, 0.f, 0.f, 0.f);
    float4* a = (float4*)g_agg;
    for (long long t = i; t < (long long)N_NODES * 16; t += stride) a[t] = z;
    for (long long t = i; t < N_NODES; t += stride) g_deg[t] = 0.f;
    float4* p = (float4*)g_pool;
    for (long long t = i; t < (long long)N_GRAPHS * 16; t += stride) p[t] = z;
    for (long long t = i; t < N_GRAPHS; t += stride) g_cnt[t] = 0.f;
}

__global__ __launch_bounds__(256) void k_zero_agg() {
    long long i = (long long)blockIdx.x * blockDim.x + threadIdx.x;
    long long stride = (long long)gridDim.x * blockDim.x;
    float4 z = make_float4(0.f, 0.f, 0.f, 0.f);
    float4* a = (float4*)g_agg;
    for (long long t = i; t < (long long)N_NODES * 16; t += stride) a[t] = z;
}

// ---------------------------------------------------------------------------
// Layer-1 scatter: agg[dst][0:32] += x[src][0:32]; deg[dst] += 1
// 8 threads per edge, one float4 each.
// ---------------------------------------------------------------------------
__global__ __launch_bounds__(256) void k_scatter1(const float* __restrict__ x,
                                                  const int* __restrict__ ei) {
    long long tid = (long long)blockIdx.x * blockDim.x + threadIdx.x;
    long long edge = tid >> 3;
    int c = (int)(tid & 7);
    if (edge >= N_EDGES) return;
    int s = __ldg(ei + edge);
    int d = __ldg(ei + N_EDGES + edge);
    float4 v = __ldg((const float4*)(x + (long long)s * 32) + c);
    red_add_v4(g_agg + (long long)d * 32 + c * 4, v);
    if (c == 0) atomicAdd(&g_deg[d], 1.0f);
}

// ---------------------------------------------------------------------------
// Layer-2 scatter: agg[dst][0:64] += h1[src][0:64]
// 16 threads per edge, one float4 each.
// ---------------------------------------------------------------------------
__global__ __launch_bounds__(256) void k_scatter2(const int* __restrict__ ei) {
    long long tid = (long long)blockIdx.x * blockDim.x + threadIdx.x;
    long long edge = tid >> 4;
    int c = (int)(tid & 15);
    if (edge >= N_EDGES) return;
    int s = __ldg(ei + edge);
    int d = __ldg(ei + N_EDGES + edge);
    float4 v = __ldg((const float4*)(g_h1 + (long long)s * 64) + c);
    red_add_v4(g_agg + (long long)d * 64 + c * 4, v);
}

// ---------------------------------------------------------------------------
// Transform 1: h1 = relu((agg/max(deg,1)) @ W1_l.T + b1 + x @ W1_r.T)
// 256 threads = 4 nodes x 64 output dims per iteration.
// Weights in shared, padded stride 33 (conflict-free when lanes sweep j).
// ---------------------------------------------------------------------------
__global__ __launch_bounds__(256) void k_transform1(const float* __restrict__ x,
                                                     const float* __restrict__ W_l,
                                                     const float* __restrict__ b,
                                                     const float* __restrict__ W_r) {
    __shared__ float sWl[64 * 33];
    __shared__ float sWr[64 * 33];
    __shared__ float sMean[4][32];
    __shared__ float sX[4][32];
    int tid = threadIdx.x;
    for (int i = tid; i < 64 * 32; i += 256) {
        int j = i >> 5, k = i & 31;
        sWl[j * 33 + k] = W_l[i];
        sWr[j * 33 + k] = W_r[i];
    }
    int nl = tid >> 6;      // node slot 0..3
    int j  = tid & 63;      // output dim
    float bj = b[j];
    __syncthreads();

    for (long long base = (long long)blockIdx.x * 4; base < N_NODES;
         base += (long long)gridDim.x * 4) {
        {   // stage: threads 0..127 load mean, 128..255 load x
            int which = tid >> 7;
            int li = tid & 127;
            int n2 = li >> 5, k = li & 31;
            long long n = base + n2;
            if (n < N_NODES) {
                if (which == 0) {
                    float inv = 1.0f / fmaxf(g_deg[n], 1.0f);
                    sMean[n2][k] = g_agg[n * 32 + k] * inv;
                } else {
                    sX[n2][k] = x[n * 32 + k];
                }
            }
        }
        __syncthreads();
        long long n = base + nl;
        if (n < N_NODES) {
            float acc = bj;
            #pragma unroll
            for (int k = 0; k < 32; k++)
                acc += sMean[nl][k] * sWl[j * 33 + k] + sX[nl][k] * sWr[j * 33 + k];
            g_h1[n * 64 + j] = fmaxf(acc, 0.0f);
        }
        __syncthreads();
    }
}

// ---------------------------------------------------------------------------
// Transform 2 + pool: h2 = relu((agg/max(deg,1)) @ W2_l.T + b2 + h1 @ W2_r.T);
// pool[batch[n]] += h2; cnt[batch[n]] += 1
// ---------------------------------------------------------------------------
__global__ __launch_bounds__(256) void k_transform2(const float* __restrict__ W_l,
                                                     const float* __restrict__ b,
                                                     const float* __restrict__ W_r,
                                                     const int* __restrict__ batch) {
    __shared__ float sWl[64 * 65];
    __shared__ float sWr[64 * 65];
    __shared__ float sMean[4][64];
    __shared__ float sH[4][64];
    int tid = threadIdx.x;
    for (int i = tid; i < 64 * 64; i += 256) {
        int j = i >> 6, k = i & 63;
        sWl[j * 65 + k] = W_l[i];
        sWr[j * 65 + k] = W_r[i];
    }
    int nl = tid >> 6;
    int j  = tid & 63;
    float bj = b[j];
    __syncthreads();

    for (long long base = (long long)blockIdx.x * 4; base < N_NODES;
         base += (long long)gridDim.x * 4) {
        {   // stage: thread (n2, k) loads both mean and h1
            int n2 = tid >> 6, k = tid & 63;
            long long n = base + n2;
            if (n < N_NODES) {
                float inv = 1.0f / fmaxf(g_deg[n], 1.0f);
                sMean[n2][k] = g_agg[n * 64 + k] * inv;
                sH[n2][k]    = g_h1[n * 64 + k];
            }
        }
        __syncthreads();
        long long n = base + nl;
        if (n < N_NODES) {
            float acc = bj;
            #pragma unroll
            for (int k = 0; k < 64; k++)
                acc += sMean[nl][k] * sWl[j * 65 + k] + sH[nl][k] * sWr[j * 65 + k];
            acc = fmaxf(acc, 0.0f);
            int g = __ldg(batch + n);
            atomicAdd(&g_pool[(long long)g * 64 + j], acc);
            if (j == 0) atomicAdd(&g_cnt[g], 1.0f);
        }
        __syncthreads();
    }
}

// ---------------------------------------------------------------------------
// Head: out[g] = (pool[g]/max(cnt,1)) @ W_lin.T + b_lin      [4000, 2]
// ---------------------------------------------------------------------------
__global__ __launch_bounds__(256) void k_final(const float* __restrict__ W_lin,
                                                const float* __restrict__ b_lin,
                                                float* __restrict__ out) {
    int g = blockIdx.x * blockDim.x + threadIdx.x;
    if (g >= N_GRAPHS) return;
    float inv = 1.0f / fmaxf(g_cnt[g], 1.0f);
    float a0 = 0.f, a1 = 0.f;
    #pragma unroll
    for (int j = 0; j < 64; j++) {
        float p = g_pool[g * 64 + j] * inv;
        a0 += p * __ldg(W_lin + j);
        a1 += p * __ldg(W_lin + 64 + j);
    }
    out[g * 2 + 0] = a0 + __ldg(b_lin + 0);
    out[g * 2 + 1] = a1 + __ldg(b_lin + 1);
}

// ---------------------------------------------------------------------------
extern "C" void kernel_launch(void* const* d_in, const int* in_sizes, int n_in,
                              void* d_out, int out_size) {
    const float* x     = (const float*)d_in[0];
    const int*   ei    = (const int*)d_in[1];
    const int*   batch = (const int*)d_in[2];
    const float* W1_l  = (const float*)d_in[3];
    const float* b1    = (const float*)d_in[4];
    const float* W1_r  = (const float*)d_in[5];
    const float* W2_l  = (const float*)d_in[6];
    const float* b2    = (const float*)d_in[7];
    const float* W2_r  = (const float*)d_in[8];
    const float* W_lin = (const float*)d_in[9];
    const float* b_lin = (const float*)d_in[10];
    float* out = (float*)d_out;

    k_zero_all<<<2048, 256>>>();
    k_scatter1<<<(int)(((long long)N_EDGES * 8 + 255) / 256), 256>>>(x, ei);
    k_transform1<<<2048, 256>>>(x, W1_l, b1, W1_r);
    k_zero_agg<<<2048, 256>>>();
    k_scatter2<<<(int)(((long long)N_EDGES * 16 + 255) / 256), 256>>>(ei);
    k_transform2<<<2048, 256>>>(W2_l, b2, W2_r, batch);
    k_final<<<(N_GRAPHS + 255) / 256, 256>>>(W_lin, b_lin, out);
}

// round 4
// speedup vs baseline: 1.7200x; 1.7200x over previous
#include <cuda_runtime.h>
#include <cuda_bf16.h>

#define N_NODES    200000
#define N_EDGES    3200000
#define N_GRAPHS   4000
#define SCAN_ELEMS 2048
#define SCAN_NBLK  ((N_NODES + SCAN_ELEMS - 1) / SCAN_ELEMS)   // 98

// ---------------- device scratch (no runtime allocation) --------------------
__device__ int   g_count[N_NODES];
__device__ int   g_rowptr[N_NODES + 1];
__device__ int   g_cursor[N_NODES];
__device__ int   g_bsums[SCAN_NBLK];
__device__ int   g_srclist[N_EDGES];
__device__ float g_agg[N_NODES * 64];     // mean aggregate (32-wide L1, 64-wide L2)
__device__ float g_h1 [N_NODES * 64];     // relu(conv1)
__device__ float g_pool[N_GRAPHS * 64];
__device__ float g_cnt [N_GRAPHS];

// ---------------------------------------------------------------------------
// Zero the small stuff: counts, pool, cnt
// ---------------------------------------------------------------------------
__global__ __launch_bounds__(256) void k_zero_small() {
    int i = blockIdx.x * blockDim.x + threadIdx.x;
    int stride = gridDim.x * blockDim.x;
    for (int t = i; t < N_NODES; t += stride) g_count[t] = 0;
    for (int t = i; t < N_GRAPHS * 64; t += stride) g_pool[t] = 0.f;
    for (int t = i; t < N_GRAPHS; t += stride) g_cnt[t] = 0.f;
}

// ---------------------------------------------------------------------------
// CSR build: histogram of dst
// ---------------------------------------------------------------------------
__global__ __launch_bounds__(256) void k_hist(const int* __restrict__ ei) {
    int e = blockIdx.x * blockDim.x + threadIdx.x;
    if (e >= N_EDGES) return;
    atomicAdd(&g_count[__ldg(ei + N_EDGES + e)], 1);
}

// ---------------------------------------------------------------------------
// Scan pass 1: per-block exclusive scan of counts (2048 elems / block of 512)
// ---------------------------------------------------------------------------
__global__ __launch_bounds__(512) void k_scan1() {
    __shared__ int warp_sums[16];
    int t = threadIdx.x;
    int base = blockIdx.x * SCAN_ELEMS + t * 4;
    int c0 = (base + 0 < N_NODES) ? g_count[base + 0] : 0;
    int c1 = (base + 1 < N_NODES) ? g_count[base + 1] : 0;
    int c2 = (base + 2 < N_NODES) ? g_count[base + 2] : 0;
    int c3 = (base + 3 < N_NODES) ? g_count[base + 3] : 0;
    int s = c0 + c1 + c2 + c3;
    int lane = t & 31, wid = t >> 5;
    int v = s;
    #pragma unroll
    for (int o = 1; o < 32; o <<= 1) {
        int u = __shfl_up_sync(0xFFFFFFFFu, v, o);
        if (lane >= o) v += u;
    }
    if (lane == 31) warp_sums[wid] = v;
    __syncthreads();
    if (wid == 0) {
        int w = (lane < 16) ? warp_sums[lane] : 0;
        #pragma unroll
        for (int o = 1; o < 16; o <<= 1) {
            int u = __shfl_up_sync(0xFFFFFFFFu, w, o);
            if (lane >= o) w += u;
        }
        if (lane < 16) warp_sums[lane] = w;
    }
    __syncthreads();
    int excl = v - s + (wid > 0 ? warp_sums[wid - 1] : 0);
    if (base + 0 < N_NODES) g_rowptr[base + 0] = excl;
    if (base + 1 < N_NODES) g_rowptr[base + 1] = excl + c0;
    if (base + 2 < N_NODES) g_rowptr[base + 2] = excl + c0 + c1;
    if (base + 3 < N_NODES) g_rowptr[base + 3] = excl + c0 + c1 + c2;
    if (t == 511) g_bsums[blockIdx.x] = warp_sums[15];
}

// Scan pass 2: exclusive scan of 98 block sums (single block)
__global__ __launch_bounds__(128) void k_scan2() {
    __shared__ int sh[128];
    int t = threadIdx.x;
    sh[t] = (t < SCAN_NBLK) ? g_bsums[t] : 0;
    __syncthreads();
    int v = sh[t];
    #pragma unroll
    for (int o = 1; o < 128; o <<= 1) {
        int u = (t >= o) ? sh[t - o] : 0;
        __syncthreads();
        v += u;
        sh[t] = v;
        __syncthreads();
    }
    if (t < SCAN_NBLK) g_bsums[t] = (t > 0) ? sh[t - 1] : 0;
}

// Scan pass 3: add block offsets, init cursors
__global__ __launch_bounds__(256) void k_scan3() {
    int i = blockIdx.x * blockDim.x + threadIdx.x;
    if (i == 0) g_rowptr[N_NODES] = N_EDGES;
    if (i >= N_NODES) return;
    int v = g_rowptr[i] + g_bsums[i / SCAN_ELEMS];
    g_rowptr[i] = v;
    g_cursor[i] = v;
}

// CSR fill
__global__ __launch_bounds__(256) void k_fill(const int* __restrict__ ei) {
    int e = blockIdx.x * blockDim.x + threadIdx.x;
    if (e >= N_EDGES) return;
    int s = __ldg(ei + e);
    int d = __ldg(ei + N_EDGES + e);
    int pos = atomicAdd(&g_cursor[d], 1);
    g_srclist[pos] = s;
}

// ---------------------------------------------------------------------------
// Layer-1 aggregation (gather): g_agg[n][0:32] = mean of x[src][0:32]
// One warp per node; lane = feature dim.
// ---------------------------------------------------------------------------
__global__ __launch_bounds__(256) void k_agg1(const float* __restrict__ x) {
    int gw = (blockIdx.x * blockDim.x + threadIdx.x) >> 5;
    int lane = threadIdx.x & 31;
    if (gw >= N_NODES) return;
    int beg = __ldg(g_rowptr + gw), end = __ldg(g_rowptr + gw + 1);
    float acc = 0.f;
    int e = beg;
    for (; e + 4 <= end; e += 4) {
        int s0 = __ldg(g_srclist + e + 0);
        int s1 = __ldg(g_srclist + e + 1);
        int s2 = __ldg(g_srclist + e + 2);
        int s3 = __ldg(g_srclist + e + 3);
        float a0 = __ldg(x + (long long)s0 * 32 + lane);
        float a1 = __ldg(x + (long long)s1 * 32 + lane);
        float a2 = __ldg(x + (long long)s2 * 32 + lane);
        float a3 = __ldg(x + (long long)s3 * 32 + lane);
        acc += (a0 + a1) + (a2 + a3);
    }
    for (; e < end; ++e)
        acc += __ldg(x + (long long)__ldg(g_srclist + e) * 32 + lane);
    float inv = 1.f / fmaxf((float)(end - beg), 1.f);
    g_agg[(long long)gw * 32 + lane] = acc * inv;
}

// ---------------------------------------------------------------------------
// Layer-2 aggregation (gather): g_agg[n][0:64] = mean of h1[src][0:64]
// One warp per node; lane handles float2 at 2*lane.
// ---------------------------------------------------------------------------
__global__ __launch_bounds__(256) void k_agg2() {
    int gw = (blockIdx.x * blockDim.x + threadIdx.x) >> 5;
    int lane = threadIdx.x & 31;
    if (gw >= N_NODES) return;
    int beg = __ldg(g_rowptr + gw), end = __ldg(g_rowptr + gw + 1);
    float ax = 0.f, ay = 0.f;
    int e = beg;
    for (; e + 4 <= end; e += 4) {
        int s0 = __ldg(g_srclist + e + 0);
        int s1 = __ldg(g_srclist + e + 1);
        int s2 = __ldg(g_srclist + e + 2);
        int s3 = __ldg(g_srclist + e + 3);
        float2 v0 = __ldg((const float2*)(g_h1 + (long long)s0 * 64) + lane);
        float2 v1 = __ldg((const float2*)(g_h1 + (long long)s1 * 64) + lane);
        float2 v2 = __ldg((const float2*)(g_h1 + (long long)s2 * 64) + lane);
        float2 v3 = __ldg((const float2*)(g_h1 + (long long)s3 * 64) + lane);
        ax += (v0.x + v1.x) + (v2.x + v3.x);
        ay += (v0.y + v1.y) + (v2.y + v3.y);
    }
    for (; e < end; ++e) {
        float2 v = __ldg((const float2*)(g_h1 + (long long)__ldg(g_srclist + e) * 64) + lane);
        ax += v.x; ay += v.y;
    }
    float inv = 1.f / fmaxf((float)(end - beg), 1.f);
    float2 r; r.x = ax * inv; r.y = ay * inv;
    ((float2*)(g_agg + (long long)gw * 64))[lane] = r;
}

// ---------------------------------------------------------------------------
// Transform 1: h1 = relu(mean @ W1_l.T + b1 + x @ W1_r.T)
// Block: 256 thr = 4 groups x 64 j; each thread 8 nodes -> 32 nodes/block.
// Weights k-major in shared (stride 65, conflict-free); activations float4.
// ---------------------------------------------------------------------------
__global__ __launch_bounds__(256) void k_transform1(const float* __restrict__ x,
                                                    const float* __restrict__ W_l,
                                                    const float* __restrict__ b,
                                                    const float* __restrict__ W_r) {
    __shared__ float sWlT[32 * 65];
    __shared__ float sWrT[32 * 65];
    __shared__ __align__(16) float sM[32][32];
    __shared__ __align__(16) float sX[32][32];
    int tid = threadIdx.x;
    for (int i = tid; i < 64 * 32; i += 256) {
        int j = i >> 5, k = i & 31;
        sWlT[k * 65 + j] = W_l[i];
        sWrT[k * 65 + j] = W_r[i];
    }
    int grp = tid >> 6;         // 0..3
    int j   = tid & 63;
    int uB  = grp * 8;
    float bj = __ldg(b + j);
    int nb32 = blockIdx.x * 32;

    // stage 32 nodes of mean + x
    for (int idx = tid; idx < 32 * 32; idx += 256) {
        int u = idx >> 5, k = idx & 31;
        int n = nb32 + u;
        sM[u][k] = g_agg[(long long)n * 32 + k];
        sX[u][k] = __ldg(x + (long long)n * 32 + k);
    }
    __syncthreads();

    float acc[8];
    #pragma unroll
    for (int u = 0; u < 8; u++) acc[u] = bj;

    #pragma unroll
    for (int k = 0; k < 32; k += 4) {
        float wl0 = sWlT[(k + 0) * 65 + j], wl1 = sWlT[(k + 1) * 65 + j];
        float wl2 = sWlT[(k + 2) * 65 + j], wl3 = sWlT[(k + 3) * 65 + j];
        float wr0 = sWrT[(k + 0) * 65 + j], wr1 = sWrT[(k + 1) * 65 + j];
        float wr2 = sWrT[(k + 2) * 65 + j], wr3 = sWrT[(k + 3) * 65 + j];
        #pragma unroll
        for (int u = 0; u < 8; u++) {
            float4 m = *(const float4*)&sM[uB + u][k];
            float4 v = *(const float4*)&sX[uB + u][k];
            acc[u] += m.x * wl0 + m.y * wl1 + m.z * wl2 + m.w * wl3
                    + v.x * wr0 + v.y * wr1 + v.z * wr2 + v.w * wr3;
        }
    }
    #pragma unroll
    for (int u = 0; u < 8; u++) {
        int n = nb32 + uB + u;
        g_h1[(long long)n * 64 + j] = fmaxf(acc[u], 0.f);
    }
}

// ---------------------------------------------------------------------------
// Transform 2 + pool: h2 = relu(mean @ W2_l.T + b2 + h1 @ W2_r.T)
// pooled directly (batch sorted -> run-length merge before atomics).
// ---------------------------------------------------------------------------
__global__ __launch_bounds__(256) void k_transform2(const float* __restrict__ W_l,
                                                    const float* __restrict__ b,
                                                    const float* __restrict__ W_r,
                                                    const int* __restrict__ batch) {
    __shared__ float sWlT[64 * 65];
    __shared__ float sWrT[64 * 65];
    __shared__ __align__(16) float sM[32][64];
    __shared__ __align__(16) float sH[32][64];
    int tid = threadIdx.x;
    for (int i = tid; i < 64 * 64; i += 256) {
        int j = i >> 6, k = i & 63;
        sWlT[k * 65 + j] = W_l[i];
        sWrT[k * 65 + j] = W_r[i];
    }
    int grp = tid >> 6;
    int j   = tid & 63;
    int uB  = grp * 8;
    float bj = __ldg(b + j);
    int nb32 = blockIdx.x * 32;

    for (int idx = tid; idx < 32 * 64; idx += 256) {
        int u = idx >> 6, k = idx & 63;
        int n = nb32 + u;
        sM[u][k] = g_agg[(long long)n * 64 + k];
        sH[u][k] = g_h1[(long long)n * 64 + k];
    }
    __syncthreads();

    float acc[8];
    #pragma unroll
    for (int u = 0; u < 8; u++) acc[u] = bj;

    #pragma unroll
    for (int k = 0; k < 64; k += 4) {
        float wl0 = sWlT[(k + 0) * 65 + j], wl1 = sWlT[(k + 1) * 65 + j];
        float wl2 = sWlT[(k + 2) * 65 + j], wl3 = sWlT[(k + 3) * 65 + j];
        float wr0 = sWrT[(k + 0) * 65 + j], wr1 = sWrT[(k + 1) * 65 + j];
        float wr2 = sWrT[(k + 2) * 65 + j], wr3 = sWrT[(k + 3) * 65 + j];
        #pragma unroll
        for (int u = 0; u < 8; u++) {
            float4 m = *(const float4*)&sM[uB + u][k];
            float4 h = *(const float4*)&sH[uB + u][k];
            acc[u] += m.x * wl0 + m.y * wl1 + m.z * wl2 + m.w * wl3
                    + h.x * wr0 + h.y * wr1 + h.z * wr2 + h.w * wr3;
        }
    }

    // pool with run-length merge (batch is sorted)
    int nb = nb32 + uB;
    int gcur = __ldg(batch + nb);
    float run = 0.f;
    #pragma unroll
    for (int u = 0; u < 8; u++) {
        float v = fmaxf(acc[u], 0.f);
        int g = __ldg(batch + nb + u);
        if (g != gcur) {
            atomicAdd(&g_pool[(long long)gcur * 64 + j], run);
            run = v; gcur = g;
        } else {
            run += v;
        }
    }
    atomicAdd(&g_pool[(long long)gcur * 64 + j], run);
}

// node-count histogram per graph
__global__ __launch_bounds__(256) void k_cnt(const int* __restrict__ batch) {
    int n = blockIdx.x * blockDim.x + threadIdx.x;
    if (n >= N_NODES) return;
    atomicAdd(&g_cnt[__ldg(batch + n)], 1.0f);
}

// ---------------------------------------------------------------------------
// Head: out[g] = (pool[g]/max(cnt,1)) @ W_lin.T + b_lin
// ---------------------------------------------------------------------------
__global__ __launch_bounds__(256) void k_final(const float* __restrict__ W_lin,
                                               const float* __restrict__ b_lin,
                                               float* __restrict__ out) {
    int g = blockIdx.x * blockDim.x + threadIdx.x;
    if (g >= N_GRAPHS) return;
    float inv = 1.0f / fmaxf(g_cnt[g], 1.0f);
    float a0 = 0.f, a1 = 0.f;
    #pragma unroll
    for (int j = 0; j < 64; j++) {
        float p = g_pool[g * 64 + j] * inv;
        a0 += p * __ldg(W_lin + j);
        a1 += p * __ldg(W_lin + 64 + j);
    }
    out[g * 2 + 0] = a0 + __ldg(b_lin + 0);
    out[g * 2 + 1] = a1 + __ldg(b_lin + 1);
}

// ---------------------------------------------------------------------------
extern "C" void kernel_launch(void* const* d_in, const int* in_sizes, int n_in,
                              void* d_out, int out_size) {
    const float* x     = (const float*)d_in[0];
    const int*   ei    = (const int*)d_in[1];
    const int*   batch = (const int*)d_in[2];
    const float* W1_l  = (const float*)d_in[3];
    const float* b1    = (const float*)d_in[4];
    const float* W1_r  = (const float*)d_in[5];
    const float* W2_l  = (const float*)d_in[6];
    const float* b2    = (const float*)d_in[7];
    const float* W2_r  = (const float*)d_in[8];
    const float* W_lin = (const float*)d_in[9];
    const float* b_lin = (const float*)d_in[10];
    float* out = (float*)d_out;

    k_zero_small<<<512, 256>>>();
    k_hist<<<(N_EDGES + 255) / 256, 256>>>(ei);
    k_scan1<<<SCAN_NBLK, 512>>>();
    k_scan2<<<1, 128>>>();
    k_scan3<<<(N_NODES + 255) / 256, 256>>>();
    k_fill<<<(N_EDGES + 255) / 256, 256>>>(ei);
    k_agg1<<<(N_NODES * 32 + 255) / 256, 256>>>(x);
    k_transform1<<<N_NODES / 32, 256>>>(x, W1_l, b1, W1_r);
    k_agg2<<<(N_NODES * 32 + 255) / 256, 256>>>();
    k_transform2<<<N_NODES / 32, 256>>>(W2_l, b2, W2_r, batch);
    k_cnt<<<(N_NODES + 255) / 256, 256>>>(batch);
    k_final<<<(N_GRAPHS + 255) / 256, 256>>>(W_lin, b_lin, out);
}

// round 5
// speedup vs baseline: 1.8456x; 1.0730x over previous
#include <cuda_runtime.h>
#include <cuda_bf16.h>

#define N_NODES    200000
#define N_EDGES    3200000
#define N_GRAPHS   4000
#define SCAN_ELEMS 2048
#define SCAN_NBLK  ((N_NODES + SCAN_ELEMS - 1) / SCAN_ELEMS)   // 98

// ---------------- device scratch (no runtime allocation) --------------------
__device__ int   g_count[N_NODES];
__device__ int   g_rowptr[N_NODES + 1];
__device__ int   g_cursor[N_NODES];
__device__ int   g_bsums[SCAN_NBLK];
__device__ int   g_srclist[N_EDGES];
__device__ float g_h1 [N_NODES * 64];     // relu(conv1)
__device__ float g_pool[N_GRAPHS * 64];

// ---------------------------------------------------------------------------
__global__ __launch_bounds__(256) void k_zero_small() {
    int i = blockIdx.x * blockDim.x + threadIdx.x;
    int stride = gridDim.x * blockDim.x;
    for (int t = i; t < N_NODES; t += stride) g_count[t] = 0;
    for (int t = i; t < N_GRAPHS * 64; t += stride) g_pool[t] = 0.f;
}

// ---------------------------------------------------------------------------
// CSR build: histogram of dst
// ---------------------------------------------------------------------------
__global__ __launch_bounds__(256) void k_hist(const int* __restrict__ ei) {
    int e = blockIdx.x * blockDim.x + threadIdx.x;
    if (e >= N_EDGES) return;
    atomicAdd(&g_count[__ldg(ei + N_EDGES + e)], 1);
}

// Scan pass 1: per-block exclusive scan of counts (2048 elems / block of 512)
__global__ __launch_bounds__(512) void k_scan1() {
    __shared__ int warp_sums[16];
    int t = threadIdx.x;
    int base = blockIdx.x * SCAN_ELEMS + t * 4;
    int c0 = (base + 0 < N_NODES) ? g_count[base + 0] : 0;
    int c1 = (base + 1 < N_NODES) ? g_count[base + 1] : 0;
    int c2 = (base + 2 < N_NODES) ? g_count[base + 2] : 0;
    int c3 = (base + 3 < N_NODES) ? g_count[base + 3] : 0;
    int s = c0 + c1 + c2 + c3;
    int lane = t & 31, wid = t >> 5;
    int v = s;
    #pragma unroll
    for (int o = 1; o < 32; o <<= 1) {
        int u = __shfl_up_sync(0xFFFFFFFFu, v, o);
        if (lane >= o) v += u;
    }
    if (lane == 31) warp_sums[wid] = v;
    __syncthreads();
    if (wid == 0) {
        int w = (lane < 16) ? warp_sums[lane] : 0;
        #pragma unroll
        for (int o = 1; o < 16; o <<= 1) {
            int u = __shfl_up_sync(0xFFFFFFFFu, w, o);
            if (lane >= o) w += u;
        }
        if (lane < 16) warp_sums[lane] = w;
    }
    __syncthreads();
    int excl = v - s + (wid > 0 ? warp_sums[wid - 1] : 0);
    if (base + 0 < N_NODES) g_rowptr[base + 0] = excl;
    if (base + 1 < N_NODES) g_rowptr[base + 1] = excl + c0;
    if (base + 2 < N_NODES) g_rowptr[base + 2] = excl + c0 + c1;
    if (base + 3 < N_NODES) g_rowptr[base + 3] = excl + c0 + c1 + c2;
    if (t == 511) g_bsums[blockIdx.x] = warp_sums[15];
}

// Scan pass 2: exclusive scan of 98 block sums (single block)
__global__ __launch_bounds__(128) void k_scan2() {
    __shared__ int sh[128];
    int t = threadIdx.x;
    sh[t] = (t < SCAN_NBLK) ? g_bsums[t] : 0;
    __syncthreads();
    int v = sh[t];
    #pragma unroll
    for (int o = 1; o < 128; o <<= 1) {
        int u = (t >= o) ? sh[t - o] : 0;
        __syncthreads();
        v += u;
        sh[t] = v;
        __syncthreads();
    }
    if (t < SCAN_NBLK) g_bsums[t] = (t > 0) ? sh[t - 1] : 0;
}

// Scan pass 3: add block offsets, init cursors
__global__ __launch_bounds__(256) void k_scan3() {
    int i = blockIdx.x * blockDim.x + threadIdx.x;
    if (i == 0) g_rowptr[N_NODES] = N_EDGES;
    if (i >= N_NODES) return;
    int v = g_rowptr[i] + g_bsums[i / SCAN_ELEMS];
    g_rowptr[i] = v;
    g_cursor[i] = v;
}

// CSR fill
__global__ __launch_bounds__(256) void k_fill(const int* __restrict__ ei) {
    int e = blockIdx.x * blockDim.x + threadIdx.x;
    if (e >= N_EDGES) return;
    int s = __ldg(ei + e);
    int d = __ldg(ei + N_EDGES + e);
    int pos = atomicAdd(&g_cursor[d], 1);
    g_srclist[pos] = s;
}

// ---------------------------------------------------------------------------
// Fused conv1: per block, 8 warps each gather-mean 4 nodes (32-dim, lane=dim)
// into shared, then register-blocked transform:
//   h1 = relu(mean @ W1_l.T + b1 + x @ W1_r.T)
// ---------------------------------------------------------------------------
__global__ __launch_bounds__(256) void k_conv1(const float* __restrict__ x,
                                               const float* __restrict__ W_l,
                                               const float* __restrict__ b,
                                               const float* __restrict__ W_r) {
    __shared__ float sWlT[32 * 65];   // k-major, [k][j] stride 65
    __shared__ float sWrT[32 * 65];
    __shared__ __align__(16) float sM[32][32];
    __shared__ __align__(16) float sX[32][32];
    int tid  = threadIdx.x;
    int w    = tid >> 5;
    int lane = tid & 31;
    int nb32 = blockIdx.x * 32;

    for (int i = tid; i < 64 * 32; i += 256) {
        int j = i >> 5, k = i & 31;
        sWlT[k * 65 + j] = W_l[i];
        sWrT[k * 65 + j] = W_r[i];
    }

    // gather phase: warp w handles nodes w*4 .. w*4+3
    #pragma unroll
    for (int u = 0; u < 4; u++) {
        int n = nb32 + w * 4 + u;
        int beg = __ldg(g_rowptr + n), end = __ldg(g_rowptr + n + 1);
        float acc = 0.f;
        int e = beg;
        for (; e + 4 <= end; e += 4) {
            int s0 = __ldg(g_srclist + e + 0);
            int s1 = __ldg(g_srclist + e + 1);
            int s2 = __ldg(g_srclist + e + 2);
            int s3 = __ldg(g_srclist + e + 3);
            float a0 = __ldg(x + (long long)s0 * 32 + lane);
            float a1 = __ldg(x + (long long)s1 * 32 + lane);
            float a2 = __ldg(x + (long long)s2 * 32 + lane);
            float a3 = __ldg(x + (long long)s3 * 32 + lane);
            acc += (a0 + a1) + (a2 + a3);
        }
        for (; e < end; ++e)
            acc += __ldg(x + (long long)__ldg(g_srclist + e) * 32 + lane);
        float inv = 1.f / fmaxf((float)(end - beg), 1.f);
        sM[w * 4 + u][lane] = acc * inv;
        sX[w * 4 + u][lane] = __ldg(x + (long long)n * 32 + lane);
    }
    __syncthreads();

    int grp = tid >> 6;         // 0..3
    int j   = tid & 63;
    int uB  = grp * 8;
    float bj = __ldg(b + j);

    float acc[8];
    #pragma unroll
    for (int u = 0; u < 8; u++) acc[u] = bj;

    #pragma unroll
    for (int k = 0; k < 32; k += 4) {
        float wl0 = sWlT[(k + 0) * 65 + j], wl1 = sWlT[(k + 1) * 65 + j];
        float wl2 = sWlT[(k + 2) * 65 + j], wl3 = sWlT[(k + 3) * 65 + j];
        float wr0 = sWrT[(k + 0) * 65 + j], wr1 = sWrT[(k + 1) * 65 + j];
        float wr2 = sWrT[(k + 2) * 65 + j], wr3 = sWrT[(k + 3) * 65 + j];
        #pragma unroll
        for (int u = 0; u < 8; u++) {
            float4 m = *(const float4*)&sM[uB + u][k];
            float4 v = *(const float4*)&sX[uB + u][k];
            acc[u] += m.x * wl0 + m.y * wl1 + m.z * wl2 + m.w * wl3
                    + v.x * wr0 + v.y * wr1 + v.z * wr2 + v.w * wr3;
        }
    }
    #pragma unroll
    for (int u = 0; u < 8; u++) {
        int n = nb32 + uB + u;
        g_h1[(long long)n * 64 + j] = fmaxf(acc[u], 0.f);
    }
}

// ---------------------------------------------------------------------------
// Fused conv2 + pool: 8 warps each gather-mean 4 nodes (64-dim, float2 lanes)
// into shared, then transform:
//   h2 = relu(mean @ W2_l.T + b2 + h1 @ W2_r.T); pool[batch[n]] += h2
// ---------------------------------------------------------------------------
__global__ __launch_bounds__(256) void k_conv2pool(const float* __restrict__ W_l,
                                                   const float* __restrict__ b,
                                                   const float* __restrict__ W_r,
                                                   const int* __restrict__ batch) {
    __shared__ float sWlT[64 * 65];
    __shared__ float sWrT[64 * 65];
    __shared__ __align__(16) float sM[32][64];
    __shared__ __align__(16) float sH[32][64];
    int tid  = threadIdx.x;
    int w    = tid >> 5;
    int lane = tid & 31;
    int nb32 = blockIdx.x * 32;

    for (int i = tid; i < 64 * 64; i += 256) {
        int j = i >> 6, k = i & 63;
        sWlT[k * 65 + j] = W_l[i];
        sWrT[k * 65 + j] = W_r[i];
    }

    #pragma unroll
    for (int u = 0; u < 4; u++) {
        int n = nb32 + w * 4 + u;
        int beg = __ldg(g_rowptr + n), end = __ldg(g_rowptr + n + 1);
        float ax = 0.f, ay = 0.f;
        int e = beg;
        for (; e + 4 <= end; e += 4) {
            int s0 = __ldg(g_srclist + e + 0);
            int s1 = __ldg(g_srclist + e + 1);
            int s2 = __ldg(g_srclist + e + 2);
            int s3 = __ldg(g_srclist + e + 3);
            float2 v0 = __ldg((const float2*)(g_h1 + (long long)s0 * 64) + lane);
            float2 v1 = __ldg((const float2*)(g_h1 + (long long)s1 * 64) + lane);
            float2 v2 = __ldg((const float2*)(g_h1 + (long long)s2 * 64) + lane);
            float2 v3 = __ldg((const float2*)(g_h1 + (long long)s3 * 64) + lane);
            ax += (v0.x + v1.x) + (v2.x + v3.x);
            ay += (v0.y + v1.y) + (v2.y + v3.y);
        }
        for (; e < end; ++e) {
            float2 v = __ldg((const float2*)(g_h1 + (long long)__ldg(g_srclist + e) * 64) + lane);
            ax += v.x; ay += v.y;
        }
        float inv = 1.f / fmaxf((float)(end - beg), 1.f);
        sM[w * 4 + u][lane * 2 + 0] = ax * inv;
        sM[w * 4 + u][lane * 2 + 1] = ay * inv;
        float2 hs = __ldg((const float2*)(g_h1 + (long long)n * 64) + lane);
        sH[w * 4 + u][lane * 2 + 0] = hs.x;
        sH[w * 4 + u][lane * 2 + 1] = hs.y;
    }
    __syncthreads();

    int grp = tid >> 6;
    int j   = tid & 63;
    int uB  = grp * 8;
    float bj = __ldg(b + j);

    float acc[8];
    #pragma unroll
    for (int u = 0; u < 8; u++) acc[u] = bj;

    #pragma unroll
    for (int k = 0; k < 64; k += 4) {
        float wl0 = sWlT[(k + 0) * 65 + j], wl1 = sWlT[(k + 1) * 65 + j];
        float wl2 = sWlT[(k + 2) * 65 + j], wl3 = sWlT[(k + 3) * 65 + j];
        float wr0 = sWrT[(k + 0) * 65 + j], wr1 = sWrT[(k + 1) * 65 + j];
        float wr2 = sWrT[(k + 2) * 65 + j], wr3 = sWrT[(k + 3) * 65 + j];
        #pragma unroll
        for (int u = 0; u < 8; u++) {
            float4 m = *(const float4*)&sM[uB + u][k];
            float4 h = *(const float4*)&sH[uB + u][k];
            acc[u] += m.x * wl0 + m.y * wl1 + m.z * wl2 + m.w * wl3
                    + h.x * wr0 + h.y * wr1 + h.z * wr2 + h.w * wr3;
        }
    }

    // pool with run-length merge (batch is sorted)
    int nb = nb32 + uB;
    int gcur = __ldg(batch + nb);
    float run = 0.f;
    #pragma unroll
    for (int u = 0; u < 8; u++) {
        float v = fmaxf(acc[u], 0.f);
        int g = __ldg(batch + nb + u);
        if (g != gcur) {
            atomicAdd(&g_pool[(long long)gcur * 64 + j], run);
            run = v; gcur = g;
        } else {
            run += v;
        }
    }
    atomicAdd(&g_pool[(long long)gcur * 64 + j], run);
}

// ---------------------------------------------------------------------------
// Head: out[g] = (pool[g]/cnt[g]) @ W_lin.T + b_lin; cnt via binary search
// (batch is sorted ascending).
// ---------------------------------------------------------------------------
__device__ __forceinline__ int lowerb(const int* __restrict__ a, int n, int v) {
    int lo = 0, hi = n;
    while (lo < hi) {
        int m = (lo + hi) >> 1;
        if (__ldg(a + m) < v) lo = m + 1; else hi = m;
    }
    return lo;
}

__global__ __launch_bounds__(256) void k_final(const float* __restrict__ W_lin,
                                               const float* __restrict__ b_lin,
                                               const int* __restrict__ batch,
                                               float* __restrict__ out) {
    int g = blockIdx.x * blockDim.x + threadIdx.x;
    if (g >= N_GRAPHS) return;
    int cnt = lowerb(batch, N_NODES, g + 1) - lowerb(batch, N_NODES, g);
    float inv = 1.0f / fmaxf((float)cnt, 1.0f);
    float a0 = 0.f, a1 = 0.f;
    #pragma unroll
    for (int j = 0; j < 64; j++) {
        float p = g_pool[g * 64 + j] * inv;
        a0 += p * __ldg(W_lin + j);
        a1 += p * __ldg(W_lin + 64 + j);
    }
    out[g * 2 + 0] = a0 + __ldg(b_lin + 0);
    out[g * 2 + 1] = a1 + __ldg(b_lin + 1);
}

// ---------------------------------------------------------------------------
extern "C" void kernel_launch(void* const* d_in, const int* in_sizes, int n_in,
                              void* d_out, int out_size) {
    const float* x     = (const float*)d_in[0];
    const int*   ei    = (const int*)d_in[1];
    const int*   batch = (const int*)d_in[2];
    const float* W1_l  = (const float*)d_in[3];
    const float* b1    = (const float*)d_in[4];
    const float* W1_r  = (const float*)d_in[5];
    const float* W2_l  = (const float*)d_in[6];
    const float* b2    = (const float*)d_in[7];
    const float* W2_r  = (const float*)d_in[8];
    const float* W_lin = (const float*)d_in[9];
    const float* b_lin = (const float*)d_in[10];
    float* out = (float*)d_out;

    k_zero_small<<<512, 256>>>();
    k_hist<<<(N_EDGES + 255) / 256, 256>>>(ei);
    k_scan1<<<SCAN_NBLK, 512>>>();
    k_scan2<<<1, 128>>>();
    k_scan3<<<(N_NODES + 255) / 256, 256>>>();
    k_fill<<<(N_EDGES + 255) / 256, 256>>>(ei);
    k_conv1<<<N_NODES / 32, 256>>>(x, W1_l, b1, W1_r);
    k_conv2pool<<<N_NODES / 32, 256>>>(W2_l, b2, W2_r, batch);
    k_final<<<(N_GRAPHS + 255) / 256, 256>>>(W_lin, b_lin, batch, out);
}

// round 10
// speedup vs baseline: 1.9100x; 1.0349x over previous
#include <cuda_runtime.h>
#include <cuda_fp16.h>

#define N_NODES    200000
#define N_EDGES    3200000
#define N_GRAPHS   4000
#define SCAN_ELEMS 2048
#define SCAN_NBLK  ((N_NODES + SCAN_ELEMS - 1) / SCAN_ELEMS)   // 98

// ---------------- device scratch (no runtime allocation) --------------------
__device__ int    g_count[N_NODES];
__device__ int    g_rowptr[N_NODES + 1];
__device__ int    g_bsums[SCAN_NBLK];
__device__ int    g_rank[N_EDGES];
__device__ int    g_srclist[N_EDGES];
__device__ __half g_h1[N_NODES * 64];     // relu(conv1), fp16
__device__ float  g_pool[N_GRAPHS * 64];

// ---------------------------------------------------------------------------
__global__ __launch_bounds__(256) void k_zero_small() {
    int i = blockIdx.x * blockDim.x + threadIdx.x;
    int stride = gridDim.x * blockDim.x;
    for (int t = i; t < N_NODES; t += stride) g_count[t] = 0;
    for (int t = i; t < N_GRAPHS * 64; t += stride) g_pool[t] = 0.f;
}

// ---------------------------------------------------------------------------
// CSR build: histogram of dst; atomic return value IS the within-bucket rank.
// 4 edges per thread via int4.
// ---------------------------------------------------------------------------
__global__ __launch_bounds__(256) void k_hist(const int* __restrict__ ei) {
    int t = blockIdx.x * blockDim.x + threadIdx.x;
    int e = t * 4;
    if (e >= N_EDGES) return;
    int4 d4 = __ldg((const int4*)(ei + N_EDGES) + t);
    g_rank[e + 0] = atomicAdd(&g_count[d4.x], 1);
    g_rank[e + 1] = atomicAdd(&g_count[d4.y], 1);
    g_rank[e + 2] = atomicAdd(&g_count[d4.z], 1);
    g_rank[e + 3] = atomicAdd(&g_count[d4.w], 1);
}

// Scan pass 1: per-block exclusive scan of counts (2048 elems / block of 512)
__global__ __launch_bounds__(512) void k_scan1() {
    __shared__ int warp_sums[16];
    int t = threadIdx.x;
    int base = blockIdx.x * SCAN_ELEMS + t * 4;
    int c0 = (base + 0 < N_NODES) ? g_count[base + 0] : 0;
    int c1 = (base + 1 < N_NODES) ? g_count[base + 1] : 0;
    int c2 = (base + 2 < N_NODES) ? g_count[base + 2] : 0;
    int c3 = (base + 3 < N_NODES) ? g_count[base + 3] : 0;
    int s = c0 + c1 + c2 + c3;
    int lane = t & 31, wid = t >> 5;
    int v = s;
    #pragma unroll
    for (int o = 1; o < 32; o <<= 1) {
        int u = __shfl_up_sync(0xFFFFFFFFu, v, o);
        if (lane >= o) v += u;
    }
    if (lane == 31) warp_sums[wid] = v;
    __syncthreads();
    if (wid == 0) {
        int w = (lane < 16) ? warp_sums[lane] : 0;
        #pragma unroll
        for (int o = 1; o < 16; o <<= 1) {
            int u = __shfl_up_sync(0xFFFFFFFFu, w, o);
            if (lane >= o) w += u;
        }
        if (lane < 16) warp_sums[lane] = w;
    }
    __syncthreads();
    int excl = v - s + (wid > 0 ? warp_sums[wid - 1] : 0);
    if (base + 0 < N_NODES) g_rowptr[base + 0] = excl;
    if (base + 1 < N_NODES) g_rowptr[base + 1] = excl + c0;
    if (base + 2 < N_NODES) g_rowptr[base + 2] = excl + c0 + c1;
    if (base + 3 < N_NODES) g_rowptr[base + 3] = excl + c0 + c1 + c2;
    if (t == 511) g_bsums[blockIdx.x] = warp_sums[15];
}

// Scan pass 2: exclusive scan of 98 block sums (single block)
__global__ __launch_bounds__(128) void k_scan2() {
    __shared__ int sh[128];
    int t = threadIdx.x;
    sh[t] = (t < SCAN_NBLK) ? g_bsums[t] : 0;
    __syncthreads();
    int v = sh[t];
    #pragma unroll
    for (int o = 1; o < 128; o <<= 1) {
        int u = (t >= o) ? sh[t - o] : 0;
        __syncthreads();
        v += u;
        sh[t] = v;
        __syncthreads();
    }
    if (t < SCAN_NBLK) g_bsums[t] = (t > 0) ? sh[t - 1] : 0;
}

// Scan pass 3: add block offsets
__global__ __launch_bounds__(256) void k_scan3() {
    int i = blockIdx.x * blockDim.x + threadIdx.x;
    if (i == 0) g_rowptr[N_NODES] = N_EDGES;
    if (i >= N_NODES) return;
    g_rowptr[i] += g_bsums[i / SCAN_ELEMS];
}

// CSR fill, atomic-free: pos = rowptr[dst] + rank[e]
__global__ __launch_bounds__(256) void k_fill(const int* __restrict__ ei) {
    int e = blockIdx.x * blockDim.x + threadIdx.x;
    if (e >= N_EDGES) return;
    int s = __ldg(ei + e);
    int d = __ldg(ei + N_EDGES + e);
    int pos = __ldg(g_rowptr + d) + __ldg(g_rank + e);
    g_srclist[pos] = s;
}

// ---------------------------------------------------------------------------
// Fused conv1: per block, 8 warps each gather-mean 4 nodes (32-dim, lane=dim)
// into shared, then register-blocked transform:
//   h1 = relu(mean @ W1_l.T + b1 + x @ W1_r.T)   (h1 stored fp16)
// ---------------------------------------------------------------------------
__global__ __launch_bounds__(256) void k_conv1(const float* __restrict__ x,
                                               const float* __restrict__ W_l,
                                               const float* __restrict__ b,
                                               const float* __restrict__ W_r) {
    __shared__ float sWlT[32 * 65];   // k-major, [k][j] stride 65
    __shared__ float sWrT[32 * 65];
    __shared__ __align__(16) float sM[32][32];
    __shared__ __align__(16) float sX[32][32];
    int tid  = threadIdx.x;
    int w    = tid >> 5;
    int lane = tid & 31;
    int nb32 = blockIdx.x * 32;

    for (int i = tid; i < 64 * 32; i += 256) {
        int j = i >> 5, k = i & 31;
        sWlT[k * 65 + j] = W_l[i];
        sWrT[k * 65 + j] = W_r[i];
    }

    // gather phase: warp w handles nodes w*4 .. w*4+3, edges unrolled x8
    #pragma unroll
    for (int u = 0; u < 4; u++) {
        int n = nb32 + w * 4 + u;
        int beg = __ldg(g_rowptr + n), end = __ldg(g_rowptr + n + 1);
        float acc = 0.f;
        int e = beg;
        for (; e + 8 <= end; e += 8) {
            int s0 = __ldg(g_srclist + e + 0);
            int s1 = __ldg(g_srclist + e + 1);
            int s2 = __ldg(g_srclist + e + 2);
            int s3 = __ldg(g_srclist + e + 3);
            int s4 = __ldg(g_srclist + e + 4);
            int s5 = __ldg(g_srclist + e + 5);
            int s6 = __ldg(g_srclist + e + 6);
            int s7 = __ldg(g_srclist + e + 7);
            float a0 = __ldg(x + (long long)s0 * 32 + lane);
            float a1 = __ldg(x + (long long)s1 * 32 + lane);
            float a2 = __ldg(x + (long long)s2 * 32 + lane);
            float a3 = __ldg(x + (long long)s3 * 32 + lane);
            float a4 = __ldg(x + (long long)s4 * 32 + lane);
            float a5 = __ldg(x + (long long)s5 * 32 + lane);
            float a6 = __ldg(x + (long long)s6 * 32 + lane);
            float a7 = __ldg(x + (long long)s7 * 32 + lane);
            acc += ((a0 + a1) + (a2 + a3)) + ((a4 + a5) + (a6 + a7));
        }
        for (; e < end; ++e)
            acc += __ldg(x + (long long)__ldg(g_srclist + e) * 32 + lane);
        float inv = 1.f / fmaxf((float)(end - beg), 1.f);
        sM[w * 4 + u][lane] = acc * inv;
        sX[w * 4 + u][lane] = __ldg(x + (long long)n * 32 + lane);
    }
    __syncthreads();

    int grp = tid >> 6;         // 0..3
    int j   = tid & 63;
    int uB  = grp * 8;
    float bj = __ldg(b + j);

    float acc[8];
    #pragma unroll
    for (int u = 0; u < 8; u++) acc[u] = bj;

    #pragma unroll
    for (int k = 0; k < 32; k += 4) {
        float wl0 = sWlT[(k + 0) * 65 + j], wl1 = sWlT[(k + 1) * 65 + j];
        float wl2 = sWlT[(k + 2) * 65 + j], wl3 = sWlT[(k + 3) * 65 + j];
        float wr0 = sWrT[(k + 0) * 65 + j], wr1 = sWrT[(k + 1) * 65 + j];
        float wr2 = sWrT[(k + 2) * 65 + j], wr3 = sWrT[(k + 3) * 65 + j];
        #pragma unroll
        for (int u = 0; u < 8; u++) {
            float4 m = *(const float4*)&sM[uB + u][k];
            float4 v = *(const float4*)&sX[uB + u][k];
            acc[u] += m.x * wl0 + m.y * wl1 + m.z * wl2 + m.w * wl3
                    + v.x * wr0 + v.y * wr1 + v.z * wr2 + v.w * wr3;
        }
    }
    #pragma unroll
    for (int u = 0; u < 8; u++) {
        int n = nb32 + uB + u;
        g_h1[(long long)n * 64 + j] = __float2half(fmaxf(acc[u], 0.f));
    }
}

// ---------------------------------------------------------------------------
// Fused conv2 + pool: 8 warps each gather-mean 4 nodes (64-dim, half2 lanes)
// then transform: h2 = relu(mean @ W2_l.T + b2 + h1 @ W2_r.T); pool += h2
// ---------------------------------------------------------------------------
__global__ __launch_bounds__(256) void k_conv2pool(const float* __restrict__ W_l,
                                                   const float* __restrict__ b,
                                                   const float* __restrict__ W_r,
                                                   const int* __restrict__ batch) {
    __shared__ float sWlT[64 * 65];
    __shared__ float sWrT[64 * 65];
    __shared__ __align__(16) float sM[32][64];
    __shared__ __align__(16) float sH[32][64];
    int tid  = threadIdx.x;
    int w    = tid >> 5;
    int lane = tid & 31;
    int nb32 = blockIdx.x * 32;

    for (int i = tid; i < 64 * 64; i += 256) {
        int j = i >> 6, k = i & 63;
        sWlT[k * 65 + j] = W_l[i];
        sWrT[k * 65 + j] = W_r[i];
    }

    #pragma unroll
    for (int u = 0; u < 4; u++) {
        int n = nb32 + w * 4 + u;
        int beg = __ldg(g_rowptr + n), end = __ldg(g_rowptr + n + 1);
        float ax = 0.f, ay = 0.f;
        int e = beg;
        for (; e + 8 <= end; e += 8) {
            int s0 = __ldg(g_srclist + e + 0);
            int s1 = __ldg(g_srclist + e + 1);
            int s2 = __ldg(g_srclist + e + 2);
            int s3 = __ldg(g_srclist + e + 3);
            int s4 = __ldg(g_srclist + e + 4);
            int s5 = __ldg(g_srclist + e + 5);
            int s6 = __ldg(g_srclist + e + 6);
            int s7 = __ldg(g_srclist + e + 7);
            float2 v0 = __half22float2(__ldg((const __half2*)(g_h1 + (long long)s0 * 64) + lane));
            float2 v1 = __half22float2(__ldg((const __half2*)(g_h1 + (long long)s1 * 64) + lane));
            float2 v2 = __half22float2(__ldg((const __half2*)(g_h1 + (long long)s2 * 64) + lane));
            float2 v3 = __half22float2(__ldg((const __half2*)(g_h1 + (long long)s3 * 64) + lane));
            float2 v4 = __half22float2(__ldg((const __half2*)(g_h1 + (long long)s4 * 64) + lane));
            float2 v5 = __half22float2(__ldg((const __half2*)(g_h1 + (long long)s5 * 64) + lane));
            float2 v6 = __half22float2(__ldg((const __half2*)(g_h1 + (long long)s6 * 64) + lane));
            float2 v7 = __half22float2(__ldg((const __half2*)(g_h1 + (long long)s7 * 64) + lane));
            ax += ((v0.x + v1.x) + (v2.x + v3.x)) + ((v4.x + v5.x) + (v6.x + v7.x));
            ay += ((v0.y + v1.y) + (v2.y + v3.y)) + ((v4.y + v5.y) + (v6.y + v7.y));
        }
        for (; e < end; ++e) {
            float2 v = __half22float2(
                __ldg((const __half2*)(g_h1 + (long long)__ldg(g_srclist + e) * 64) + lane));
            ax += v.x; ay += v.y;
        }
        float inv = 1.f / fmaxf((float)(end - beg), 1.f);
        sM[w * 4 + u][lane * 2 + 0] = ax * inv;
        sM[w * 4 + u][lane * 2 + 1] = ay * inv;
        float2 hs = __half22float2(__ldg((const __half2*)(g_h1 + (long long)n * 64) + lane));
        sH[w * 4 + u][lane * 2 + 0] = hs.x;
        sH[w * 4 + u][lane * 2 + 1] = hs.y;
    }
    __syncthreads();

    int grp = tid >> 6;
    int j   = tid & 63;
    int uB  = grp * 8;
    float bj = __ldg(b + j);

    float acc[8];
    #pragma unroll
    for (int u = 0; u < 8; u++) acc[u] = bj;

    #pragma unroll
    for (int k = 0; k < 64; k += 4) {
        float wl0 = sWlT[(k + 0) * 65 + j], wl1 = sWlT[(k + 1) * 65 + j];
        float wl2 = sWlT[(k + 2) * 65 + j], wl3 = sWlT[(k + 3) * 65 + j];
        float wr0 = sWrT[(k + 0) * 65 + j], wr1 = sWrT[(k + 1) * 65 + j];
        float wr2 = sWrT[(k + 2) * 65 + j], wr3 = sWrT[(k + 3) * 65 + j];
        #pragma unroll
        for (int u = 0; u < 8; u++) {
            float4 m = *(const float4*)&sM[uB + u][k];
            float4 h = *(const float4*)&sH[uB + u][k];
            acc[u] += m.x * wl0 + m.y * wl1 + m.z * wl2 + m.w * wl3
                    + h.x * wr0 + h.y * wr1 + h.z * wr2 + h.w * wr3;
        }
    }

    // pool with run-length merge (batch is sorted)
    int nb = nb32 + uB;
    int gcur = __ldg(batch + nb);
    float run = 0.f;
    #pragma unroll
    for (int u = 0; u < 8; u++) {
        float v = fmaxf(acc[u], 0.f);
        int g = __ldg(batch + nb + u);
        if (g != gcur) {
            atomicAdd(&g_pool[(long long)gcur * 64 + j], run);
            run = v; gcur = g;
        } else {
            run += v;
        }
    }
    atomicAdd(&g_pool[(long long)gcur * 64 + j], run);
}

// ---------------------------------------------------------------------------
// Head: out[g] = (pool[g]/cnt[g]) @ W_lin.T + b_lin; cnt via binary search
// ---------------------------------------------------------------------------
__device__ __forceinline__ int lowerb(const int* __restrict__ a, int n, int v) {
    int lo = 0, hi = n;
    while (lo < hi) {
        int m = (lo + hi) >> 1;
        if (__ldg(a + m) < v) lo = m + 1; else hi = m;
    }
    return lo;
}

__global__ __launch_bounds__(256) void k_final(const float* __restrict__ W_lin,
                                               const float* __restrict__ b_lin,
                                               const int* __restrict__ batch,
                                               float* __restrict__ out) {
    int g = blockIdx.x * blockDim.x + threadIdx.x;
    if (g >= N_GRAPHS) return;
    int cnt = lowerb(batch, N_NODES, g + 1) - lowerb(batch, N_NODES, g);
    float inv = 1.0f / fmaxf((float)cnt, 1.0f);
    float a0 = 0.f, a1 = 0.f;
    #pragma unroll
    for (int j = 0; j < 64; j++) {
        float p = g_pool[g * 64 + j] * inv;
        a0 += p * __ldg(W_lin + j);
        a1 += p * __ldg(W_lin + 64 + j);
    }
    out[g * 2 + 0] = a0 + __ldg(b_lin + 0);
    out[g * 2 + 1] = a1 + __ldg(b_lin + 1);
}

// ---------------------------------------------------------------------------
extern "C" void kernel_launch(void* const* d_in, const int* in_sizes, int n_in,
                              void* d_out, int out_size) {
    const float* x     = (const float*)d_in[0];
    const int*   ei    = (const int*)d_in[1];
    const int*   batch = (const int*)d_in[2];
    const float* W1_l  = (const float*)d_in[3];
    const float* b1    = (const float*)d_in[4];
    const float* W1_r  = (const float*)d_in[5];
    const float* W2_l  = (const float*)d_in[6];
    const float* b2    = (const float*)d_in[7];
    const float* W2_r  = (const float*)d_in[8];
    const float* W_lin = (const float*)d_in[9];
    const float* b_lin = (const float*)d_in[10];
    float* out = (float*)d_out;

    k_zero_small<<<512, 256>>>();
    k_hist<<<(N_EDGES / 4 + 255) / 256, 256>>>(ei);
    k_scan1<<<SCAN_NBLK, 512>>>();
    k_scan2<<<1, 128>>>();
    k_scan3<<<(N_NODES + 255) / 256, 256>>>();
    k_fill<<<(N_EDGES + 255) / 256, 256>>>(ei);
    k_conv1<<<N_NODES / 32, 256>>>(x, W1_l, b1, W1_r);
    k_conv2pool<<<N_NODES / 32, 256>>>(W2_l, b2, W2_r, batch);
    k_final<<<(N_GRAPHS + 255) / 256, 256>>>(W_lin, b_lin, batch, out);
}